// round 11
// baseline (speedup 1.0000x reference)
#include <cuda_runtime.h>

// CRF negative log-likelihood, L=64 live states, exp-domain recursion.
// TWO batches interleaved per thread: the independent chains fill each
// other's latency bubbles (bar skew, LDS, FFMA dep tails).
//
//   v_t[j]  = (sum_i v_{t-1}[i] * E[i][j]) * exp(pred[b,t-1,j]) * 2^{-ex_t}
//   E[i][j] = exp(trans[i][j]);  ex_t = float exponent of v_{t-1}[0]
//   logZ_b  = m0 + ks*ln2 + log( sum_j v_seq[j] * exp(trans[j][65]) )
//   gold_b  = sum_t pred[b,t,ref_t] + trans[64][ref_0]
//           + sum trans[ref_{t-1}][ref_t] + trans[ref_{seq-1}][65]
//
// 64 threads per CTA (state j = tid), grid = ceil(B/2): batch A = blockIdx,
// batch B = blockIdx + B/2. E-matrix registers shared by both chains.

__device__ double g_partial[4096];
__device__ int    g_count;   // static zero-init; last CTA resets each run

__device__ __forceinline__ float warp_rmax(float v) {
#pragma unroll
    for (int o = 16; o > 0; o >>= 1)
        v = fmaxf(v, __shfl_xor_sync(0xffffffffu, v, o));
    return v;
}
__device__ __forceinline__ float warp_rsum(float v) {
#pragma unroll
    for (int o = 16; o > 0; o >>= 1)
        v += __shfl_xor_sync(0xffffffffu, v, o);
    return v;
}

typedef unsigned long long u64;
__device__ __forceinline__ u64 ffma2(u64 a, u64 b, u64 c) {
    u64 d;
    asm("fma.rn.f32x2 %0, %1, %2, %3;" : "=l"(d) : "l"(a), "l"(b), "l"(c));
    return d;
}
__device__ __forceinline__ u64 fadd2(u64 a, u64 b) {
    u64 d;
    asm("add.rn.f32x2 %0, %1, %2;" : "=l"(d) : "l"(a), "l"(b));
    return d;
}
__device__ __forceinline__ u64 pack2(float lo, float hi) {
    u64 d;
    asm("mov.b64 %0, {%1, %2};" : "=l"(d) : "f"(lo), "f"(hi));
    return d;
}
__device__ __forceinline__ float sum2(u64 a0, u64 a1, u64 a2, u64 a3) {
    u64 s2 = fadd2(fadd2(a0, a2), fadd2(a1, a3));
    float lo, hi;
    asm("mov.b64 {%0, %1}, %2;" : "=f"(lo), "=f"(hi) : "l"(s2));
    return lo + hi;
}

__global__ void __launch_bounds__(64)
crf_kernel(const float* __restrict__ pred,
           const float* __restrict__ trans,
           const int*   __restrict__ ref,
           const int*   __restrict__ slen,
           float* __restrict__ out,
           int B, int T, int out_size)
{
    __shared__ float4 eA[2][16];    // double-buffered v vectors
    __shared__ float4 eB[2][16];
    __shared__ float  fin[8];
    __shared__ double red[64];
    __shared__ int    s_last;

    const int j    = threadIdx.x;   // state column, 0..63
    const int wih  = j >> 5;
    const int lane = j & 31;

    const int bA   = blockIdx.x;
    const int half = (B + 1) >> 1;
    const int bBr  = bA + half;
    const bool hasB = (bBr < B);
    const int bB   = hasB ? bBr : bA;

    const float* pA = pred + (size_t)bA * T * 64;
    const float* pB = pred + (size_t)bB * T * 64;
    const int*   rA = ref  + (size_t)bA * T;
    const int*   rB = ref  + (size_t)bB * T;
    const int seqA = slen[bA];
    const int seqB = slen[bB];

    // E column j as 32 packed f32x2 pairs (shared by both chains)
    u64 E2[32];
#pragma unroll
    for (int p = 0; p < 32; ++p)
        E2[p] = pack2(__expf(trans[(2 * p) * 66 + j]),
                      __expf(trans[(2 * p + 1) * 66 + j]));

    // ---- gold path scores ----
    float goldA = 0.0f, goldB = 0.0f;
    {
        int nkA = (seqA - j + 63) >> 6;
#pragma unroll 4
        for (int k = 0; k < nkA; ++k) {
            int t  = j + (k << 6);
            int r  = rA[t];
            int rp = (t == 0) ? 64 : rA[t - 1];
            float g = pA[(size_t)t * 64 + r] + trans[rp * 66 + r];
            if (t == seqA - 1) g += trans[r * 66 + 65];
            goldA += g;
        }
        int nkB = (seqB - j + 63) >> 6;
#pragma unroll 4
        for (int k = 0; k < nkB; ++k) {
            int t  = j + (k << 6);
            int r  = rB[t];
            int rp = (t == 0) ? 64 : rB[t - 1];
            float g = pB[(size_t)t * 64 + r] + trans[rp * 66 + r];
            if (t == seqB - 1) g += trans[r * 66 + 65];
            goldB += g;
        }
    }

    // ---- bootstrap: v_1 = exp(alpha_1 - m0) for both chains ----
    float tS = trans[64 * 66 + j];
    float a1A = pA[j] + tS;
    float a1B = pB[j] + tS;
    float wmA = warp_rmax(a1A);
    float wmB = warp_rmax(a1B);
    if (lane == 0) { fin[wih] = wmA; fin[2 + wih] = wmB; }
    __syncthreads();
    float m0A = fmaxf(fin[0], fin[1]);
    float m0B = fmaxf(fin[2], fin[3]);
    float vA = __expf(a1A - m0A);
    float vB = __expf(a1B - m0B);
    int ksA = 0, ksB = 0;

    // prefetch pipelines: Pc = exp(pred row t-1) consumed at step t
    float PcA = __expf(pA[(size_t)min(1, seqA - 1) * 64 + j]);
    float paA = pA[(size_t)min(2, seqA - 1) * 64 + j];
    float pbA = pA[(size_t)min(3, seqA - 1) * 64 + j];
    float PcB = __expf(pB[(size_t)min(1, seqB - 1) * 64 + j]);
    float paB = pB[(size_t)min(2, seqB - 1) * 64 + j];
    float pbB = pB[(size_t)min(3, seqB - 1) * 64 + j];

    const int tmax = max(seqA, seqB);
    int par = 0;
#pragma unroll 2
    for (int t = 2; t <= tmax; ++t) {
        // publish both v vectors
        reinterpret_cast<float*>(eA[par])[j] = vA;
        reinterpret_cast<float*>(eB[par])[j] = vB;

        // rotate prefetch BEFORE the sync (LDG/MUFU hide under barrier)
        float PnA = __expf(paA);
        float PnB = __expf(paB);
        paA = pbA;  paB = pbB;
        int tcA = (t + 2) < (seqA - 1) ? (t + 2) : (seqA - 1);
        int tcB = (t + 2) < (seqB - 1) ? (t + 2) : (seqB - 1);
        pbA = pA[(size_t)tcA * 64 + j];
        pbB = pB[(size_t)tcB * 64 + j];

        __syncthreads();

        const ulonglong2* ea = reinterpret_cast<const ulonglong2*>(eA[par]);
        const ulonglong2* eb = reinterpret_cast<const ulonglong2*>(eB[par]);

        u64 A0 = 0ull, A1 = 0ull, A2 = 0ull, A3 = 0ull;
        u64 B0 = 0ull, B1 = 0ull, B2 = 0ull, B3 = 0ull;

        // first half of both chains (keeps live vector regs bounded)
        ulonglong2 qa0 = ea[0], qa1 = ea[1], qa2 = ea[2], qa3 = ea[3];
        ulonglong2 qb0 = eb[0], qb1 = eb[1], qb2 = eb[2], qb3 = eb[3];
        A0 = ffma2(qa0.x, E2[0], A0);  B0 = ffma2(qb0.x, E2[0], B0);
        A1 = ffma2(qa0.y, E2[1], A1);  B1 = ffma2(qb0.y, E2[1], B1);
        A2 = ffma2(qa1.x, E2[2], A2);  B2 = ffma2(qb1.x, E2[2], B2);
        A3 = ffma2(qa1.y, E2[3], A3);  B3 = ffma2(qb1.y, E2[3], B3);
        A0 = ffma2(qa2.x, E2[4], A0);  B0 = ffma2(qb2.x, E2[4], B0);
        A1 = ffma2(qa2.y, E2[5], A1);  B1 = ffma2(qb2.y, E2[5], B1);
        A2 = ffma2(qa3.x, E2[6], A2);  B2 = ffma2(qb3.x, E2[6], B2);
        A3 = ffma2(qa3.y, E2[7], A3);  B3 = ffma2(qb3.y, E2[7], B3);

        // scale factors from v[0] (low float of first loaded pair) — no extra LDS
        float v0A = __uint_as_float((unsigned int)qa0.x);
        float v0B = __uint_as_float((unsigned int)qb0.x);
        int exA = (__float_as_int(v0A) >> 23) - 127;
        int exB = (__float_as_int(v0B) >> 23) - 127;
        float fA = PcA * __int_as_float((127 - exA) << 23);
        float fB = PcB * __int_as_float((127 - exB) << 23);

        // second half of both chains
        ulonglong2 ra0 = ea[4], ra1 = ea[5], ra2 = ea[6], ra3 = ea[7];
        ulonglong2 rb0 = eb[4], rb1 = eb[5], rb2 = eb[6], rb3 = eb[7];
        A0 = ffma2(ra0.x, E2[8],  A0);  B0 = ffma2(rb0.x, E2[8],  B0);
        A1 = ffma2(ra0.y, E2[9],  A1);  B1 = ffma2(rb0.y, E2[9],  B1);
        A2 = ffma2(ra1.x, E2[10], A2);  B2 = ffma2(rb1.x, E2[10], B2);
        A3 = ffma2(ra1.y, E2[11], A3);  B3 = ffma2(rb1.y, E2[11], B3);
        A0 = ffma2(ra2.x, E2[12], A0);  B0 = ffma2(rb2.x, E2[12], B0);
        A1 = ffma2(ra2.y, E2[13], A1);  B1 = ffma2(rb2.y, E2[13], B1);
        A2 = ffma2(ra3.x, E2[14], A2);  B2 = ffma2(rb3.x, E2[14], B2);
        A3 = ffma2(ra3.y, E2[15], A3);  B3 = ffma2(rb3.y, E2[15], B3);

        ulonglong2 sa0 = ea[8],  sa1 = ea[9],  sa2 = ea[10], sa3 = ea[11];
        ulonglong2 sb0 = eb[8],  sb1 = eb[9],  sb2 = eb[10], sb3 = eb[11];
        A0 = ffma2(sa0.x, E2[16], A0);  B0 = ffma2(sb0.x, E2[16], B0);
        A1 = ffma2(sa0.y, E2[17], A1);  B1 = ffma2(sb0.y, E2[17], B1);
        A2 = ffma2(sa1.x, E2[18], A2);  B2 = ffma2(sb1.x, E2[18], B2);
        A3 = ffma2(sa1.y, E2[19], A3);  B3 = ffma2(sb1.y, E2[19], B3);
        A0 = ffma2(sa2.x, E2[20], A0);  B0 = ffma2(sb2.x, E2[20], B0);
        A1 = ffma2(sa2.y, E2[21], A1);  B1 = ffma2(sb2.y, E2[21], B1);
        A2 = ffma2(sa3.x, E2[22], A2);  B2 = ffma2(sb3.x, E2[22], B2);
        A3 = ffma2(sa3.y, E2[23], A3);  B3 = ffma2(sb3.y, E2[23], B3);

        ulonglong2 ta0 = ea[12], ta1 = ea[13], ta2 = ea[14], ta3 = ea[15];
        ulonglong2 tb0 = eb[12], tb1 = eb[13], tb2 = eb[14], tb3 = eb[15];
        A0 = ffma2(ta0.x, E2[24], A0);  B0 = ffma2(tb0.x, E2[24], B0);
        A1 = ffma2(ta0.y, E2[25], A1);  B1 = ffma2(tb0.y, E2[25], B1);
        A2 = ffma2(ta1.x, E2[26], A2);  B2 = ffma2(tb1.x, E2[26], B2);
        A3 = ffma2(ta1.y, E2[27], A3);  B3 = ffma2(tb1.y, E2[27], B3);
        A0 = ffma2(ta2.x, E2[28], A0);  B0 = ffma2(tb2.x, E2[28], B0);
        A1 = ffma2(ta2.y, E2[29], A1);  B1 = ffma2(tb2.y, E2[29], B1);
        A2 = ffma2(ta3.x, E2[30], A2);  B2 = ffma2(tb3.x, E2[30], B2);
        A3 = ffma2(ta3.y, E2[31], A3);  B3 = ffma2(tb3.y, E2[31], B3);

        float sA = sum2(A0, A1, A2, A3);
        float sB = sum2(B0, B1, B2, B3);

        // predicated update (uniform per CTA; shorter chain freezes)
        if (t <= seqA) { vA = sA * fA; ksA += exA; }
        if (t <= seqB) { vB = sB * fB; ksB += exB; }

        PcA = PnA;
        PcB = PnB;
        par ^= 1;
    }

    // ---- logZ and per-batch losses ----
    float tE  = __expf(trans[j * 66 + 65]);
    float swA = warp_rsum(vA * tE);
    float swB = warp_rsum(vB * tE);
    float gsA = warp_rsum(goldA);
    float gsB = warp_rsum(goldB);
    if (lane == 0) {
        fin[wih]     = swA;  fin[2 + wih] = swB;
        fin[4 + wih] = gsA;  fin[6 + wih] = gsB;
    }
    __syncthreads();
    if (j == 0) {
        double lossA = (double)m0A + 0.6931471805599453 * (double)ksA
                     + (double)__logf(fin[0] + fin[1])
                     - (double)(fin[4] + fin[5]);
        g_partial[bA] = lossA;
        if (hasB) {
            double lossB = (double)m0B + 0.6931471805599453 * (double)ksB
                         + (double)__logf(fin[2] + fin[3])
                         - (double)(fin[6] + fin[7]);
            g_partial[bB] = lossB;
        }
        __threadfence();
        int c = atomicAdd(&g_count, 1);
        s_last = (c == (int)gridDim.x - 1) ? 1 : 0;
    }
    __syncthreads();

    // ---- last CTA: deterministic fixed-order final reduction ----
    if (s_last) {
        __threadfence();
        double s = 0.0;
        for (int i = j; i < B; i += 64) s += g_partial[i];
        red[j] = s;
        __syncthreads();
#pragma unroll
        for (int wd = 32; wd > 0; wd >>= 1) {
            if (j < wd) red[j] += red[j + wd];
            __syncthreads();
        }
        for (int i = j; i < out_size; i += 64)
            out[i] = (i == 0) ? (float)red[0] : 0.0f;
        if (j == 0) g_count = 0;   // reset for next graph replay
    }
}

extern "C" void kernel_launch(void* const* d_in, const int* in_sizes, int n_in,
                              void* d_out, int out_size)
{
    // Identify inputs by element count (robust to metadata ordering):
    //   trans = 66*66 = 4356, pred = largest, seq_len = smallest, ref = rest.
    int it = -1;
    for (int i = 0; i < n_in; ++i)
        if (in_sizes[i] == 66 * 66) { it = i; break; }
    int ip = -1, is = -1;
    for (int i = 0; i < n_in; ++i) {
        if (i == it) continue;
        if (ip < 0 || in_sizes[i] > in_sizes[ip]) ip = i;
        if (is < 0 || in_sizes[i] < in_sizes[is]) is = i;
    }
    int ir = -1;
    for (int i = 0; i < n_in; ++i)
        if (i != it && i != ip && i != is) { ir = i; break; }

    const float* pred  = (const float*)d_in[ip];
    const float* trans = (const float*)d_in[it];
    const int*   ref   = (const int*)d_in[ir];
    const int*   slen  = (const int*)d_in[is];

    const int B = in_sizes[is];
    const int T = in_sizes[ir] / B;

    int grid = (B + 1) / 2;
    crf_kernel<<<grid, 64>>>(pred, trans, ref, slen, (float*)d_out, B, T, out_size);
}

// round 12
// speedup vs baseline: 1.5491x; 1.5491x over previous
#include <cuda_runtime.h>

// CRF negative log-likelihood, L=64 live states, exp-domain recursion.
//
//   v_t[j]  = (sum_i v_{t-1}[i] * E[i][j]) * exp(pred[b,t-1,j]) * 2^{-ex_t}
//   E[i][j] = exp(trans[i][j]);  ex_t = float exponent of v_{t-1}[0]
//   logZ_b  = m0 + ks*ln2 + log( sum_j v_seq[j] * exp(trans[j][65]) )
//   gold_b  = sum_t pred[b,t,ref_t] + trans[64][ref_0]
//           + sum trans[ref_{t-1}][ref_t] + trans[ref_{seq-1}][65]
//
// Block = 128 threads = TWO batches: warps {0,1} -> batch A (SMSP 0,1),
// warps {2,3} -> batch B (SMSP 2,3) — one warp per SMSP (wid%4 mapping),
// one cheap block-wide __syncthreads per step. grid = ceil(B/2) = 1 CTA/SM.

__device__ double g_partial[4096];
__device__ int    g_count;   // static zero-init; last CTA resets each run

__device__ __forceinline__ float warp_rmax(float v) {
#pragma unroll
    for (int o = 16; o > 0; o >>= 1)
        v = fmaxf(v, __shfl_xor_sync(0xffffffffu, v, o));
    return v;
}
__device__ __forceinline__ float warp_rsum(float v) {
#pragma unroll
    for (int o = 16; o > 0; o >>= 1)
        v += __shfl_xor_sync(0xffffffffu, v, o);
    return v;
}

typedef unsigned long long u64;
__device__ __forceinline__ u64 ffma2(u64 a, u64 b, u64 c) {
    u64 d;
    asm("fma.rn.f32x2 %0, %1, %2, %3;" : "=l"(d) : "l"(a), "l"(b), "l"(c));
    return d;
}
__device__ __forceinline__ u64 fadd2(u64 a, u64 b) {
    u64 d;
    asm("add.rn.f32x2 %0, %1, %2;" : "=l"(d) : "l"(a), "l"(b));
    return d;
}
__device__ __forceinline__ u64 pack2(float lo, float hi) {
    u64 d;
    asm("mov.b64 %0, {%1, %2};" : "=l"(d) : "f"(lo), "f"(hi));
    return d;
}

__global__ void __launch_bounds__(128, 1)
crf_kernel(const float* __restrict__ pred,
           const float* __restrict__ trans,
           const int*   __restrict__ ref,
           const int*   __restrict__ slen,
           float* __restrict__ out,
           int B, int T, int out_size)
{
    __shared__ float4 ebuf[2][2][16];   // [half][parity][16] = v vector, 64 floats
    __shared__ float  fin[8];
    __shared__ double red[128];
    __shared__ int    s_last;

    const int tid  = threadIdx.x;
    const int w    = tid >> 5;          // warp 0..3  -> SMSP 0..3
    const int lane = tid & 31;
    const int hf   = w >> 1;            // batch half: warps {0,1}=0, {2,3}=1
    const int j    = ((w & 1) << 5) | lane;   // owned state 0..63

    const int  halfB = (B + 1) >> 1;
    const int  b0    = blockIdx.x;
    const int  b1r   = b0 + halfB;
    const bool has1  = (b1r < B);
    const int  b1    = has1 ? b1r : b0;
    const int  myb   = hf ? b1 : b0;
    const int  otb   = hf ? b0 : b1;

    const float* pb  = pred + (size_t)myb * T * 64;
    const int*   rb  = ref  + (size_t)myb * T;
    const int    seq = slen[myb];
    const int    tmax = max(seq, slen[otb]);

    // E column j as 32 packed f32x2 pairs
    u64 E2[32];
#pragma unroll
    for (int p = 0; p < 32; ++p)
        E2[p] = pack2(__expf(trans[(2 * p) * 66 + j]),
                      __expf(trans[(2 * p + 1) * 66 + j]));

    // ---- gold path score (64 threads of this half, distinct time steps) ----
    float gold = 0.0f;
    {
        int nk = (seq - j + 63) >> 6;
#pragma unroll 4
        for (int k = 0; k < nk; ++k) {
            int t  = j + (k << 6);
            int r  = rb[t];
            int rp = (t == 0) ? 64 : rb[t - 1];
            float g = pb[(size_t)t * 64 + r] + trans[rp * 66 + r];
            if (t == seq - 1) g += trans[r * 66 + 65];
            gold += g;
        }
    }

    // ---- bootstrap: v_1 = exp(alpha_1 - m0) ----
    float alpha1 = pb[j] + trans[64 * 66 + j];
    float wm = warp_rmax(alpha1);
    if (lane == 0) fin[w] = wm;
    __syncthreads();
    float m0 = fmaxf(fin[2 * hf], fin[2 * hf + 1]);
    float v  = __expf(alpha1 - m0);
    int   ks = 0;

    // prefetch pipeline: Pc = exp(pred row t-1) consumed at step t
    float PcV = __expf(pb[(size_t)min(1, seq - 1) * 64 + j]);
    float pa  = pb[(size_t)min(2, seq - 1) * 64 + j];
    float pbv = pb[(size_t)min(3, seq - 1) * 64 + j];
    const float* p2 = pb + (size_t)min(4, seq - 1) * 64 + j;  // row t+2 at t=2
    const int adv_lim = seq - 4;     // advance p2 while t <= seq-4

    int par = 0;
#pragma unroll 2
    for (int t = 2; t <= tmax; ++t) {
        // publish v_{t-1}
        reinterpret_cast<float*>(ebuf[hf][par])[j] = v;

        // rotate prefetch BEFORE the sync (LDG/MUFU hide under barrier)
        float Pn = __expf(pa);
        pa  = pbv;
        pbv = *p2;
        p2 += (t <= adv_lim) ? 64 : 0;

        __syncthreads();

        const ulonglong2* ev =
            reinterpret_cast<const ulonglong2*>(ebuf[hf][par]);

        u64 a0 = 0ull, a1 = 0ull, a2 = 0ull, a3 = 0ull;
        ulonglong2 q0 = ev[0];
        // scale exponent straight from the loaded register (no scalar LDS)
        float v0 = __uint_as_float((unsigned int)q0.x);
        int   ex = (__float_as_int(v0) >> 23) - 127;
        float factor = PcV * __int_as_float((127 - ex) << 23);

        a0 = ffma2(q0.x, E2[0], a0);
        a1 = ffma2(q0.y, E2[1], a1);
#pragma unroll
        for (int k = 1; k < 16; ++k) {
            ulonglong2 q = ev[k];
            if (k & 1) {
                a2 = ffma2(q.x, E2[2 * k],     a2);
                a3 = ffma2(q.y, E2[2 * k + 1], a3);
            } else {
                a0 = ffma2(q.x, E2[2 * k],     a0);
                a1 = ffma2(q.y, E2[2 * k + 1], a1);
            }
        }

        u64 s2 = fadd2(fadd2(a0, a2), fadd2(a1, a3));
        float slo, shi;
        asm("mov.b64 {%0, %1}, %2;" : "=f"(slo), "=f"(shi) : "l"(s2));

        // predicated update: frozen half (t > seq) keeps v and ks
        if (t <= seq) { v = (slo + shi) * factor; ks += ex; }

        PcV = Pn;
        par ^= 1;
    }

    // ---- logZ and per-batch loss ----
    float tE = __expf(trans[j * 66 + 65]);
    float sw = warp_rsum(v * tE);
    float gs = warp_rsum(gold);
    if (lane == 0) { fin[w] = sw; fin[4 + w] = gs; }
    __syncthreads();
    if ((tid & 63) == 0 && (hf == 0 || has1)) {   // tid 0 -> batch A, tid 64 -> batch B
        float swt = fin[2 * hf] + fin[2 * hf + 1];
        float gst = fin[4 + 2 * hf] + fin[5 + 2 * hf];
        double loss = (double)m0 + 0.6931471805599453 * (double)ks
                    + (double)__logf(swt) - (double)gst;
        g_partial[myb] = loss;
    }
    __syncthreads();
    if (tid == 0) {
        __threadfence();
        int c = atomicAdd(&g_count, 1);
        s_last = (c == (int)gridDim.x - 1) ? 1 : 0;
    }
    __syncthreads();

    // ---- last CTA: deterministic fixed-order final reduction ----
    if (s_last) {
        __threadfence();
        double s = 0.0;
        for (int i = tid; i < B; i += 128) s += g_partial[i];
        red[tid] = s;
        __syncthreads();
#pragma unroll
        for (int wd = 64; wd > 0; wd >>= 1) {
            if (tid < wd) red[tid] += red[tid + wd];
            __syncthreads();
        }
        for (int i = tid; i < out_size; i += 128)
            out[i] = (i == 0) ? (float)red[0] : 0.0f;
        if (tid == 0) g_count = 0;   // reset for next graph replay
    }
}

extern "C" void kernel_launch(void* const* d_in, const int* in_sizes, int n_in,
                              void* d_out, int out_size)
{
    // Identify inputs by element count (robust to metadata ordering):
    //   trans = 66*66 = 4356, pred = largest, seq_len = smallest, ref = rest.
    int it = -1;
    for (int i = 0; i < n_in; ++i)
        if (in_sizes[i] == 66 * 66) { it = i; break; }
    int ip = -1, is = -1;
    for (int i = 0; i < n_in; ++i) {
        if (i == it) continue;
        if (ip < 0 || in_sizes[i] > in_sizes[ip]) ip = i;
        if (is < 0 || in_sizes[i] < in_sizes[is]) is = i;
    }
    int ir = -1;
    for (int i = 0; i < n_in; ++i)
        if (i != it && i != ip && i != is) { ir = i; break; }

    const float* pred  = (const float*)d_in[ip];
    const float* trans = (const float*)d_in[it];
    const int*   ref   = (const int*)d_in[ir];
    const int*   slen  = (const int*)d_in[is];

    const int B = in_sizes[is];
    const int T = in_sizes[ir] / B;

    int grid = (B + 1) / 2;
    crf_kernel<<<grid, 128>>>(pred, trans, ref, slen, (float*)d_out, B, T, out_size);
}

// round 13
// speedup vs baseline: 1.8875x; 1.2184x over previous
#include <cuda_runtime.h>

// CRF negative log-likelihood, L=64 live states, exp-domain recursion.
// R7 topology (empirical optimum): block=64 (one batch, 2 warps),
// grid=B, 2 CTAs/SM, per-CTA __syncthreads, independent trip counts.
//
//   v_t[j]  = (sum_i v_{t-1}[i] * E[i][j]) * exp(pred[b,t-1,j]) * 2^{-ex_t}
//   E[i][j] = exp(trans[i][j]);  ex_t = float exponent of v_{t-1}[0]
//   logZ_b  = m0 + ks*ln2 + log( sum_j v_seq[j] * exp(trans[j][65]) )
//   gold_b  = sum_t pred[b,t,ref_t] + trans[64][ref_0]
//           + sum trans[ref_{t-1}][ref_t] + trans[ref_{seq-1}][65]

__device__ double g_partial[4096];
__device__ int    g_count;   // static zero-init; last CTA resets each run

__device__ __forceinline__ float warp_rmax(float v) {
#pragma unroll
    for (int o = 16; o > 0; o >>= 1)
        v = fmaxf(v, __shfl_xor_sync(0xffffffffu, v, o));
    return v;
}
__device__ __forceinline__ float warp_rsum(float v) {
#pragma unroll
    for (int o = 16; o > 0; o >>= 1)
        v += __shfl_xor_sync(0xffffffffu, v, o);
    return v;
}

typedef unsigned long long u64;
__device__ __forceinline__ u64 ffma2(u64 a, u64 b, u64 c) {
    u64 d;
    asm("fma.rn.f32x2 %0, %1, %2, %3;" : "=l"(d) : "l"(a), "l"(b), "l"(c));
    return d;
}
__device__ __forceinline__ u64 fadd2(u64 a, u64 b) {
    u64 d;
    asm("add.rn.f32x2 %0, %1, %2;" : "=l"(d) : "l"(a), "l"(b));
    return d;
}
__device__ __forceinline__ u64 pack2(float lo, float hi) {
    u64 d;
    asm("mov.b64 %0, {%1, %2};" : "=l"(d) : "f"(lo), "f"(hi));
    return d;
}

__global__ void __launch_bounds__(64, 2)
crf_kernel(const float* __restrict__ pred,
           const float* __restrict__ trans,
           const int*   __restrict__ ref,
           const int*   __restrict__ slen,
           float* __restrict__ out,
           int B, int T, int out_size)
{
    __shared__ float4 e[2][16];     // double-buffered v vector (64 floats)
    __shared__ float  fin[4];
    __shared__ double red[64];
    __shared__ int    s_last;

    const int j    = threadIdx.x;   // state column, 0..63
    const int wih  = j >> 5;
    const int lane = j & 31;
    const int b    = blockIdx.x;    // grid = B exactly

    const float* pb  = pred + (size_t)b * T * 64;
    const int*   rb  = ref  + (size_t)b * T;
    const int    seq = slen[b];

    // E column j as 32 packed f32x2 pairs
    u64 E2[32];
#pragma unroll
    for (int p = 0; p < 32; ++p)
        E2[p] = pack2(__expf(trans[(2 * p) * 66 + j]),
                      __expf(trans[(2 * p + 1) * 66 + j]));

    // ---- gold path score (parallel over time) ----
    float gold = 0.0f;
    {
        int nk = (seq - j + 63) >> 6;
#pragma unroll 4
        for (int k = 0; k < nk; ++k) {
            int t  = j + (k << 6);
            int r  = rb[t];
            int rp = (t == 0) ? 64 : rb[t - 1];
            float g = pb[(size_t)t * 64 + r] + trans[rp * 66 + r];
            if (t == seq - 1) g += trans[r * 66 + 65];
            gold += g;
        }
    }

    // ---- bootstrap: v_1 = exp(alpha_1 - m0) ----
    float alpha1 = pb[j] + trans[64 * 66 + j];
    float wm = warp_rmax(alpha1);
    if (lane == 0) fin[wih] = wm;
    __syncthreads();
    float m0 = fmaxf(fin[0], fin[1]);
    float v  = __expf(alpha1 - m0);
    int   ks = 0;

    // prefetch pipeline: PcV = exp(pred row t-1) consumed at step t;
    // pointer-bump (predicated) instead of per-step min/IMAD.
    float PcV = __expf(pb[(size_t)min(1, seq - 1) * 64 + j]);
    float pa  = pb[(size_t)min(2, seq - 1) * 64 + j];
    float pbv = pb[(size_t)min(3, seq - 1) * 64 + j];
    const float* p2 = pb + (size_t)min(4, seq - 1) * 64 + j;  // row t+2 at t=2
    const int adv_lim = seq - 4;   // advance p2 while t <= seq-4

    int par = 0;
#pragma unroll 2
    for (int t = 2; t <= seq; ++t) {
        // publish v_{t-1}
        reinterpret_cast<float*>(e[par])[j] = v;

        // rotate prefetch BEFORE the sync (LDG/MUFU hide under the barrier)
        float Pn = __expf(pa);
        pa  = pbv;
        pbv = *p2;
        p2 += (t <= adv_lim) ? 64 : 0;

        __syncthreads();

        const ulonglong2* ev = reinterpret_cast<const ulonglong2*>(e[par]);

        u64 a0 = 0ull, a1 = 0ull, a2 = 0ull, a3 = 0ull;
        ulonglong2 q0 = ev[0];

        // scale exponent straight from the loaded register (no scalar LDS)
        float v0 = __uint_as_float((unsigned int)q0.x);
        int   ex = (__float_as_int(v0) >> 23) - 127;
        float factor = PcV * __int_as_float((127 - ex) << 23);

        a0 = ffma2(q0.x, E2[0], a0);
        a1 = ffma2(q0.y, E2[1], a1);
#pragma unroll
        for (int k = 1; k < 16; ++k) {
            ulonglong2 q = ev[k];
            if (k & 1) {
                a2 = ffma2(q.x, E2[2 * k],     a2);
                a3 = ffma2(q.y, E2[2 * k + 1], a3);
            } else {
                a0 = ffma2(q.x, E2[2 * k],     a0);
                a1 = ffma2(q.y, E2[2 * k + 1], a1);
            }
        }

        u64 s2 = fadd2(fadd2(a0, a2), fadd2(a1, a3));
        float slo, shi;
        asm("mov.b64 {%0, %1}, %2;" : "=f"(slo), "=f"(shi) : "l"(s2));

        // tail: shi*factor runs in parallel with the unpack's other half
        v = fmaf(slo, factor, shi * factor);
        ks += ex;

        PcV = Pn;
        par ^= 1;
    }

    // ---- logZ and per-batch loss ----
    float tE = __expf(trans[j * 66 + 65]);
    float sw = warp_rsum(v * tE);
    float gs = warp_rsum(gold);
    if (lane == 0) { fin[wih] = sw; fin[2 + wih] = gs; }
    __syncthreads();
    if (j == 0) {
        double loss = (double)m0 + 0.6931471805599453 * (double)ks
                    + (double)__logf(fin[0] + fin[1])
                    - (double)(fin[2] + fin[3]);
        g_partial[b] = loss;
        __threadfence();
        int c = atomicAdd(&g_count, 1);
        s_last = (c == (int)gridDim.x - 1) ? 1 : 0;
    }
    __syncthreads();

    // ---- last CTA: deterministic fixed-order final reduction ----
    if (s_last) {
        __threadfence();
        double s = 0.0;
        for (int i = j; i < B; i += 64) s += g_partial[i];
        red[j] = s;
        __syncthreads();
#pragma unroll
        for (int wd = 32; wd > 0; wd >>= 1) {
            if (j < wd) red[j] += red[j + wd];
            __syncthreads();
        }
        for (int i = j; i < out_size; i += 64)
            out[i] = (i == 0) ? (float)red[0] : 0.0f;
        if (j == 0) g_count = 0;   // reset for next graph replay
    }
}

extern "C" void kernel_launch(void* const* d_in, const int* in_sizes, int n_in,
                              void* d_out, int out_size)
{
    // Identify inputs by element count (robust to metadata ordering):
    //   trans = 66*66 = 4356, pred = largest, seq_len = smallest, ref = rest.
    int it = -1;
    for (int i = 0; i < n_in; ++i)
        if (in_sizes[i] == 66 * 66) { it = i; break; }
    int ip = -1, is = -1;
    for (int i = 0; i < n_in; ++i) {
        if (i == it) continue;
        if (ip < 0 || in_sizes[i] > in_sizes[ip]) ip = i;
        if (is < 0 || in_sizes[i] < in_sizes[is]) is = i;
    }
    int ir = -1;
    for (int i = 0; i < n_in; ++i)
        if (i != it && i != ip && i != is) { ir = i; break; }

    const float* pred  = (const float*)d_in[ip];
    const float* trans = (const float*)d_in[it];
    const int*   ref   = (const int*)d_in[ir];
    const int*   slen  = (const int*)d_in[is];

    const int B = in_sizes[is];
    const int T = in_sizes[ir] / B;

    crf_kernel<<<B, 64>>>(pred, trans, ref, slen, (float*)d_out, B, T, out_size);
}

// round 14
// speedup vs baseline: 2.0573x; 1.0900x over previous
#include <cuda_runtime.h>

// CRF negative log-likelihood, L=64 live states, exp-domain recursion.
// R7 topology (measured optimum): block=64 (one batch, 2 warps), grid=B,
// per-CTA __syncthreads, independent trip counts, fused final reduction.
// R13 deltas vs R7: (1) prefetch rotate moved AFTER the barrier so it fills
// the defer-blocking wait window instead of delaying arrival; (2) pred
// prefetch depth 2 -> 3 (~600 cyc LDG cover).
//
//   v_t[j]  = (sum_i v_{t-1}[i] * E[i][j]) * exp(pred[b,t-1,j]) * 2^{-ex_t}
//   E[i][j] = exp(trans[i][j]);  ex_t = float exponent of v_{t-1}[0]
//   logZ_b  = m0 + ks*ln2 + log( sum_j v_seq[j] * exp(trans[j][65]) )
//   gold_b  = sum_t pred[b,t,ref_t] + trans[64][ref_0]
//           + sum trans[ref_{t-1}][ref_t] + trans[ref_{seq-1}][65]

__device__ double g_partial[4096];
__device__ int    g_count;   // static zero-init; last CTA resets each run

__device__ __forceinline__ float warp_rmax(float v) {
#pragma unroll
    for (int o = 16; o > 0; o >>= 1)
        v = fmaxf(v, __shfl_xor_sync(0xffffffffu, v, o));
    return v;
}
__device__ __forceinline__ float warp_rsum(float v) {
#pragma unroll
    for (int o = 16; o > 0; o >>= 1)
        v += __shfl_xor_sync(0xffffffffu, v, o);
    return v;
}

typedef unsigned long long u64;
__device__ __forceinline__ u64 ffma2(u64 a, u64 b, u64 c) {
    u64 d;
    asm("fma.rn.f32x2 %0, %1, %2, %3;" : "=l"(d) : "l"(a), "l"(b), "l"(c));
    return d;
}
__device__ __forceinline__ u64 fadd2(u64 a, u64 b) {
    u64 d;
    asm("add.rn.f32x2 %0, %1, %2;" : "=l"(d) : "l"(a), "l"(b));
    return d;
}
__device__ __forceinline__ u64 pack2(float lo, float hi) {
    u64 d;
    asm("mov.b64 %0, {%1, %2};" : "=l"(d) : "f"(lo), "f"(hi));
    return d;
}

__global__ void __launch_bounds__(64, 2)
crf_kernel(const float* __restrict__ pred,
           const float* __restrict__ trans,
           const int*   __restrict__ ref,
           const int*   __restrict__ slen,
           float* __restrict__ out,
           int B, int T, int out_size)
{
    __shared__ float4 e[2][16];     // double-buffered v vector (64 floats)
    __shared__ float  fin[4];
    __shared__ double red[64];
    __shared__ int    s_last;

    const int j    = threadIdx.x;   // state column, 0..63
    const int wih  = j >> 5;
    const int lane = j & 31;
    const int b    = blockIdx.x;    // grid = B exactly

    const float* pb  = pred + (size_t)b * T * 64;
    const int*   rb  = ref  + (size_t)b * T;
    const int    seq = slen[b];

    // E column j as 32 packed f32x2 pairs
    u64 E2[32];
#pragma unroll
    for (int p = 0; p < 32; ++p)
        E2[p] = pack2(__expf(trans[(2 * p) * 66 + j]),
                      __expf(trans[(2 * p + 1) * 66 + j]));

    // ---- gold path score (parallel over time) ----
    float gold = 0.0f;
    {
        int nk = (seq - j + 63) >> 6;
#pragma unroll 4
        for (int k = 0; k < nk; ++k) {
            int t  = j + (k << 6);
            int r  = rb[t];
            int rp = (t == 0) ? 64 : rb[t - 1];
            float g = pb[(size_t)t * 64 + r] + trans[rp * 66 + r];
            if (t == seq - 1) g += trans[r * 66 + 65];
            gold += g;
        }
    }

    // ---- bootstrap: v_1 = exp(alpha_1 - m0) ----
    float alpha1 = pb[j] + trans[64 * 66 + j];
    float wm = warp_rmax(alpha1);
    if (lane == 0) fin[wih] = wm;
    __syncthreads();
    float m0 = fmaxf(fin[0], fin[1]);
    float v  = __expf(alpha1 - m0);
    int   ks = 0;

    // prefetch pipeline, depth 3: P_cur = exp(pred row t-1) consumed at t;
    // pv_a/pv_b/pv_c hold rows t, t+1, t+2.
    float P_cur = __expf(pb[(size_t)min(1, seq - 1) * 64 + j]);
    float pv_a  = pb[(size_t)min(2, seq - 1) * 64 + j];
    float pv_b  = pb[(size_t)min(3, seq - 1) * 64 + j];
    float pv_c  = pb[(size_t)min(4, seq - 1) * 64 + j];

    int par = 0;
    for (int t = 2; t <= seq; ++t) {
        // publish v_{t-1}, arrive at the barrier immediately
        reinterpret_cast<float*>(e[par])[j] = v;
        __syncthreads();

        // prefetch rotate AFTER the bar: defer-blocking lets these LDG/MUFU
        // execute inside the barrier-wait window (first blocked op is the
        // LDS of e[par] below).
        float Pn = __expf(pv_a);
        pv_a = pv_b;
        pv_b = pv_c;
        int tn = t + 3;
        int tc = tn < seq - 1 ? tn : seq - 1;
        pv_c = pb[(size_t)tc * 64 + j];

        // uniform exact power-of-two scale from v_{t-1}[0]
        float m = reinterpret_cast<const float*>(e[par])[0];

        // s_j = sum_i v_i * E[i][j]  — 16x LDS.128 + 32x FFMA2
        const ulonglong2* evv = reinterpret_cast<const ulonglong2*>(e[par]);
        u64 a0 = 0ull, a1 = 0ull, a2 = 0ull, a3 = 0ull;
        ulonglong2 q0 = evv[0], q1 = evv[1], q2 = evv[2], q3 = evv[3];
        ulonglong2 q4 = evv[4], q5 = evv[5], q6 = evv[6], q7 = evv[7];
        a0 = ffma2(q0.x, E2[0],  a0);
        a1 = ffma2(q0.y, E2[1],  a1);
        a2 = ffma2(q1.x, E2[2],  a2);
        a3 = ffma2(q1.y, E2[3],  a3);
        a0 = ffma2(q2.x, E2[4],  a0);
        a1 = ffma2(q2.y, E2[5],  a1);
        a2 = ffma2(q3.x, E2[6],  a2);
        a3 = ffma2(q3.y, E2[7],  a3);
        a0 = ffma2(q4.x, E2[8],  a0);
        a1 = ffma2(q4.y, E2[9],  a1);
        a2 = ffma2(q5.x, E2[10], a2);
        a3 = ffma2(q5.y, E2[11], a3);
        a0 = ffma2(q6.x, E2[12], a0);
        a1 = ffma2(q6.y, E2[13], a1);
        a2 = ffma2(q7.x, E2[14], a2);
        a3 = ffma2(q7.y, E2[15], a3);
        ulonglong2 r0 = evv[8],  r1 = evv[9],  r2 = evv[10], r3 = evv[11];
        ulonglong2 r4 = evv[12], r5 = evv[13], r6 = evv[14], r7 = evv[15];
        a0 = ffma2(r0.x, E2[16], a0);
        a1 = ffma2(r0.y, E2[17], a1);
        a2 = ffma2(r1.x, E2[18], a2);
        a3 = ffma2(r1.y, E2[19], a3);
        a0 = ffma2(r2.x, E2[20], a0);
        a1 = ffma2(r2.y, E2[21], a1);
        a2 = ffma2(r3.x, E2[22], a2);
        a3 = ffma2(r3.y, E2[23], a3);
        a0 = ffma2(r4.x, E2[24], a0);
        a1 = ffma2(r4.y, E2[25], a1);
        a2 = ffma2(r5.x, E2[26], a2);
        a3 = ffma2(r5.y, E2[27], a3);
        a0 = ffma2(r6.x, E2[28], a0);
        a1 = ffma2(r6.y, E2[29], a1);
        a2 = ffma2(r7.x, E2[30], a2);
        a3 = ffma2(r7.y, E2[31], a3);

        int ex = (__float_as_int(m) >> 23) - 127;
        ks += ex;
        float factor = P_cur * __int_as_float((127 - ex) << 23);

        u64 s2 = fadd2(fadd2(a0, a2), fadd2(a1, a3));
        float slo, shi;
        asm("mov.b64 {%0, %1}, %2;" : "=f"(slo), "=f"(shi) : "l"(s2));
        v = (slo + shi) * factor;

        P_cur = Pn;
        par ^= 1;
    }

    // ---- logZ and per-batch loss ----
    float tE = __expf(trans[j * 66 + 65]);
    float sw = warp_rsum(v * tE);
    float gs = warp_rsum(gold);
    if (lane == 0) { fin[wih] = sw; fin[2 + wih] = gs; }
    __syncthreads();
    if (j == 0) {
        double loss = (double)m0 + 0.6931471805599453 * (double)ks
                    + (double)__logf(fin[0] + fin[1])
                    - (double)(fin[2] + fin[3]);
        g_partial[b] = loss;
        __threadfence();
        int c = atomicAdd(&g_count, 1);
        s_last = (c == (int)gridDim.x - 1) ? 1 : 0;
    }
    __syncthreads();

    // ---- last CTA: deterministic fixed-order final reduction ----
    if (s_last) {
        __threadfence();
        double s = 0.0;
        for (int i = j; i < B; i += 64) s += g_partial[i];
        red[j] = s;
        __syncthreads();
#pragma unroll
        for (int wd = 32; wd > 0; wd >>= 1) {
            if (j < wd) red[j] += red[j + wd];
            __syncthreads();
        }
        for (int i = j; i < out_size; i += 64)
            out[i] = (i == 0) ? (float)red[0] : 0.0f;
        if (j == 0) g_count = 0;   // reset for next graph replay
    }
}

extern "C" void kernel_launch(void* const* d_in, const int* in_sizes, int n_in,
                              void* d_out, int out_size)
{
    // Identify inputs by element count (robust to metadata ordering):
    //   trans = 66*66 = 4356, pred = largest, seq_len = smallest, ref = rest.
    int it = -1;
    for (int i = 0; i < n_in; ++i)
        if (in_sizes[i] == 66 * 66) { it = i; break; }
    int ip = -1, is = -1;
    for (int i = 0; i < n_in; ++i) {
        if (i == it) continue;
        if (ip < 0 || in_sizes[i] > in_sizes[ip]) ip = i;
        if (is < 0 || in_sizes[i] < in_sizes[is]) is = i;
    }
    int ir = -1;
    for (int i = 0; i < n_in; ++i)
        if (i != it && i != ip && i != is) { ir = i; break; }

    const float* pred  = (const float*)d_in[ip];
    const float* trans = (const float*)d_in[it];
    const int*   ref   = (const int*)d_in[ir];
    const int*   slen  = (const int*)d_in[is];

    const int B = in_sizes[is];
    const int T = in_sizes[ir] / B;

    crf_kernel<<<B, 64>>>(pred, trans, ref, slen, (float*)d_out, B, T, out_size);
}